// round 8
// baseline (speedup 1.0000x reference)
#include <cuda_runtime.h>
#include <cstdint>

// ---------------------------------------------------------------------------
// EfficientFi VQ-VAE forward, B=1024.  Round 8: weights read from global/L1
// (no smem staging) -> 2-4 CTAs/SM residency; arithmetic byte-identical to R6.
// ---------------------------------------------------------------------------

#define NB 1024
typedef unsigned long long ull;

__device__ float         g_p1[NB * 3200];
__device__ unsigned char g_i1[NB * 3200];
__device__ float         g_vq[NB * 3200];
__device__ unsigned char g_i2[NB * 2400];
__device__ int           g_ind[NB * 128];
__device__ float         g_lat[NB * 2400];
__device__ float         g_lp[128];

// ---------------- f32x2 packed helpers (sm_103a) ----------------
static __device__ __forceinline__ ull f2pk(float a, float b) {
    ull r; asm("mov.b64 %0, {%1, %2};" : "=l"(r) : "f"(a), "f"(b)); return r;
}
static __device__ __forceinline__ void f2un(ull v, float& lo, float& hi) {
    asm("mov.b64 {%0, %1}, %2;" : "=f"(lo), "=f"(hi) : "l"(v));
}
static __device__ __forceinline__ ull f2dup(float a) { return f2pk(a, a); }
static __device__ __forceinline__ ull f2mul(ull a, ull b) {
    ull d; asm("mul.rn.f32x2 %0, %1, %2;" : "=l"(d) : "l"(a), "l"(b)); return d;
}
static __device__ __forceinline__ ull f2fma(ull a, ull b, ull c) {
    ull d; asm("fma.rn.f32x2 %0, %1, %2, %3;" : "=l"(d) : "l"(a), "l"(b), "l"(c)); return d;
}
static __device__ __forceinline__ ull f2add(ull a, ull b) {
    ull d; asm("add.rn.f32x2 %0, %1, %2;" : "=l"(d) : "l"(a), "l"(b)); return d;
}
static __device__ __forceinline__ float f2sum(ull v) {
    float lo, hi; f2un(v, lo, hi); return lo + hi;
}
static __device__ __forceinline__ ull f2mid(ull a, ull b) {
    float alo, ahi, blo, bhi; f2un(a, alo, ahi); f2un(b, blo, bhi);
    return f2pk(ahi, blo);
}

// 3x3 conv on a 2x2 pooled patch (single oc) — arithmetic identical to R4/R6.
// Weights come straight from global (L1-cached, near-broadcast across warp).
template <int NIC>
static __device__ __forceinline__ void conv3x3_patch12(const float* __restrict__ tile,
                                                       const float* __restrict__ wbase,
                                                       float bias, ull& acc0, ull& acc1) {
    acc0 = f2dup(bias);
    acc1 = acc0;
#pragma unroll 4
    for (int ic = 0; ic < NIC; ++ic) {
        const float* rp = tile + ic * 144;
        ull A0 = *(const ull*)(rp);      ull B0 = *(const ull*)(rp + 2);
        ull A1 = *(const ull*)(rp + 12); ull B1 = *(const ull*)(rp + 14);
        ull A2 = *(const ull*)(rp + 24); ull B2 = *(const ull*)(rp + 26);
        ull A3 = *(const ull*)(rp + 36); ull B3 = *(const ull*)(rp + 38);
        ull M0 = f2mid(A0, B0), M1 = f2mid(A1, B1);
        ull M2 = f2mid(A2, B2), M3 = f2mid(A3, B3);
        const float* wp = wbase + ic * 9;
        ull w;
        w = f2dup(__ldg(wp + 0)); acc0 = f2fma(w, A0, acc0); acc1 = f2fma(w, A1, acc1);
        w = f2dup(__ldg(wp + 1)); acc0 = f2fma(w, M0, acc0); acc1 = f2fma(w, M1, acc1);
        w = f2dup(__ldg(wp + 2)); acc0 = f2fma(w, B0, acc0); acc1 = f2fma(w, B1, acc1);
        w = f2dup(__ldg(wp + 3)); acc0 = f2fma(w, A1, acc0); acc1 = f2fma(w, A2, acc1);
        w = f2dup(__ldg(wp + 4)); acc0 = f2fma(w, M1, acc0); acc1 = f2fma(w, M2, acc1);
        w = f2dup(__ldg(wp + 5)); acc0 = f2fma(w, B1, acc0); acc1 = f2fma(w, B2, acc1);
        w = f2dup(__ldg(wp + 6)); acc0 = f2fma(w, A2, acc0); acc1 = f2fma(w, A3, acc1);
        w = f2dup(__ldg(wp + 7)); acc0 = f2fma(w, M2, acc0); acc1 = f2fma(w, M3, acc1);
        w = f2dup(__ldg(wp + 8)); acc0 = f2fma(w, B2, acc0); acc1 = f2fma(w, B3, acc1);
    }
}

// ---------------------------------------------------------------------------
// kA: conv1 + relu + pool1.  grid=1024, block=256.  (unchanged arithmetic)
// ---------------------------------------------------------------------------
__global__ void __launch_bounds__(256) kA(const float* __restrict__ x,
                                          const float* __restrict__ w,
                                          const float* __restrict__ bias) {
    __shared__ float xp[3 * 484];
    __shared__ float ws[864];
    __shared__ float bs[32];
    const int bb = blockIdx.x;
    const int tid = threadIdx.x;

    for (int i = tid; i < 3 * 484; i += 256) xp[i] = 0.f;
    __syncthreads();
    for (int i = tid; i < 1200; i += 256) {
        int c = i / 400, r = i % 400, y = r / 20, xx = r % 20;
        xp[c * 484 + (y + 1) * 22 + (xx + 1)] = x[bb * 1200 + i];
    }
    for (int i = tid; i < 864; i += 256) ws[i] = w[i];
    if (tid < 32) bs[tid] = bias[tid];
    __syncthreads();

    for (int cell = tid; cell < 3200; cell += 256) {
        const int oc = cell / 100;
        const int r = cell % 100;
        const int py = r / 10, px = r % 10;
        float acc[2][2];
        acc[0][0] = acc[0][1] = acc[1][0] = acc[1][1] = bs[oc];
#pragma unroll
        for (int c = 0; c < 3; ++c) {
            const int base = c * 484 + (2 * py) * 22 + 2 * px;
            float in[4][4];
#pragma unroll
            for (int rr = 0; rr < 4; ++rr)
#pragma unroll
                for (int cc = 0; cc < 4; ++cc) in[rr][cc] = xp[base + rr * 22 + cc];
            const float* wp = ws + (oc * 3 + c) * 9;
#pragma unroll
            for (int kh = 0; kh < 3; ++kh)
#pragma unroll
                for (int kw = 0; kw < 3; ++kw) {
                    const float wv = wp[kh * 3 + kw];
#pragma unroll
                    for (int dy = 0; dy < 2; ++dy)
#pragma unroll
                        for (int dx = 0; dx < 2; ++dx)
                            acc[dy][dx] = fmaf(wv, in[dy + kh][dx + kw], acc[dy][dx]);
                }
        }
        float best = -1.f;
        int bi = 0;
#pragma unroll
        for (int dy = 0; dy < 2; ++dy)
#pragma unroll
            for (int dx = 0; dx < 2; ++dx) {
                float v = fmaxf(acc[dy][dx], 0.f);
                int ii = dy * 2 + dx;
                if (v > best) { best = v; bi = ii; }
            }
        g_p1[bb * 3200 + cell] = best;
        g_i1[bb * 3200 + cell] = (unsigned char)bi;
    }
}

// ---------------------------------------------------------------------------
// kB: conv2 + relu + pool2 + pre 1x1.  grid=1024, block=800.
// smem floats: p1p[4608] b2s[96] zs[2400] pbs[128] = 7232 (28928 B) -> 2 CTAs/SM
// Weights (w2, pw) read straight from global/L1.
// ---------------------------------------------------------------------------
#define SMEM_B_FLOATS (4608 + 96 + 2400 + 128)
__global__ void __launch_bounds__(800) kB(const float* __restrict__ w2,
                                          const float* __restrict__ b2,
                                          const float* __restrict__ pw,
                                          const float* __restrict__ pb) {
    extern __shared__ float sm[];
    float* p1p = sm;            // 32 x 12 x 12
    float* b2s = p1p + 4608;
    float* zs  = b2s + 96;      // 96 x 25
    float* pbs = zs + 2400;
    const int bb = blockIdx.x;
    const int tid = threadIdx.x;

    for (int i = tid; i < 4608; i += 800) p1p[i] = 0.f;
    __syncthreads();
    for (int i = tid; i < 3200; i += 800) {
        int c = i / 100, r = i % 100, y = r / 10, xx = r % 10;
        p1p[c * 144 + (y + 1) * 12 + (xx + 1)] = g_p1[bb * 3200 + i];
    }
    if (tid < 96) b2s[tid] = b2[tid];
    if (tid < 128) pbs[tid] = pb[tid];
    __syncthreads();

    // conv2+pool: 2400 items, exactly 3 per thread
    for (int cell = tid; cell < 2400; cell += 800) {
        const int oc = cell / 25;
        const int s = cell % 25;
        const int py = s / 5, px = s % 5;
        ull acc0, acc1;
        conv3x3_patch12<32>(p1p + (2 * py) * 12 + 2 * px, w2 + oc * 288, b2s[oc], acc0, acc1);
        float a00, a01, a10, a11;
        f2un(acc0, a00, a01); f2un(acc1, a10, a11);
        float v00 = fmaxf(a00, 0.f), v01 = fmaxf(a01, 0.f);
        float v10 = fmaxf(a10, 0.f), v11 = fmaxf(a11, 0.f);
        float best = v00; int bi = 0;
        if (v01 > best) { best = v01; bi = 1; }
        if (v10 > best) { best = v10; bi = 2; }
        if (v11 > best) { best = v11; bi = 3; }
        zs[oc * 25 + s] = best;
        g_i2[bb * 2400 + cell] = (unsigned char)bi;
    }
    __syncthreads();

    // pre 1x1 — arithmetic byte-identical to R4/R6 (feeds VQ argmin!)
    for (int o = tid; o < 3200; o += 800) {
        const int e = o / 25, s = o % 25;
        const float* wp = pw + e * 96;
        float a0 = 0.f, a1 = 0.f, a2 = 0.f, a3 = 0.f;
#pragma unroll 4
        for (int c = 0; c < 96; c += 4) {
            a0 = fmaf(__ldg(wp + c + 0), zs[(c + 0) * 25 + s], a0);
            a1 = fmaf(__ldg(wp + c + 1), zs[(c + 1) * 25 + s], a1);
            a2 = fmaf(__ldg(wp + c + 2), zs[(c + 2) * 25 + s], a2);
            a3 = fmaf(__ldg(wp + c + 3), zs[(c + 3) * 25 + s], a3);
        }
        g_vq[bb * 3200 + o] = (a0 + a1) + (a2 + a3) + pbs[e];
    }
}

// ---------------------------------------------------------------------------
// kD: VQ argmin. grid=128, block=1024 (single wave). smem 114688 B.
// Unchanged from R6 (byte-identical decisions).
// ---------------------------------------------------------------------------
#define SMEM_D_FLOATS (1024 * 28)
__global__ void __launch_bounds__(1024) kD(const float* __restrict__ codebook) {
    extern __shared__ float cb[];
    __shared__ float sred[32];
    const int tid = threadIdx.x;

    if (tid < 1024) {
        const int j = tid;
        float nrm = 0.f;
#pragma unroll
        for (int k = 0; k < 25; ++k) {
            float v = codebook[j * 25 + k];
            cb[j * 28 + k] = v;
            nrm = fmaf(v, v, nrm);
        }
        cb[j * 28 + 25] = 0.5f * nrm;
        cb[j * 28 + 26] = 0.f;
        cb[j * 28 + 27] = 0.f;
    }
    __syncthreads();

    const int t = blockIdx.x * 1024 + tid;
    ull fp[14];
    {
        const float* fv = g_vq + t * 25;
#pragma unroll
        for (int i = 0; i < 12; ++i) fp[i] = f2pk(fv[2 * i], fv[2 * i + 1]);
        fp[12] = f2pk(fv[24], -1.0f);
        fp[13] = f2pk(0.f, 0.f);
    }

    float best = -3.402823e38f;
    int bi = 0;
#pragma unroll 2
    for (int j = 0; j < 1024; ++j) {
        const ulonglong2* row = reinterpret_cast<const ulonglong2*>(cb + j * 28);
        ulonglong2 v0 = row[0], v1 = row[1], v2 = row[2], v3 = row[3];
        ulonglong2 v4 = row[4], v5 = row[5], v6 = row[6];
        ull a = f2mul(fp[0], v0.x);
        ull c = f2mul(fp[1], v0.y);
        a = f2fma(fp[2], v1.x, a);  c = f2fma(fp[3], v1.y, c);
        a = f2fma(fp[4], v2.x, a);  c = f2fma(fp[5], v2.y, c);
        a = f2fma(fp[6], v3.x, a);  c = f2fma(fp[7], v3.y, c);
        a = f2fma(fp[8], v4.x, a);  c = f2fma(fp[9], v4.y, c);
        a = f2fma(fp[10], v5.x, a); c = f2fma(fp[11], v5.y, c);
        a = f2fma(fp[12], v6.x, a); c = f2fma(fp[13], v6.y, c);
        float sc = f2sum(f2add(a, c));
        if (sc > best) { best = sc; bi = j; }  // strict > == first-argmin
    }
    g_ind[t] = bi;

    float ls = 0.f;
    const float* rr = cb + bi * 28;
#pragma unroll
    for (int i = 0; i < 12; ++i) {
        float lo, hi; f2un(fp[i], lo, hi);
        float d0 = rr[2 * i] - lo;     ls = fmaf(d0, d0, ls);
        float d1 = rr[2 * i + 1] - hi; ls = fmaf(d1, d1, ls);
    }
    {
        float lo, hi; f2un(fp[12], lo, hi);
        float d = rr[24] - lo; ls = fmaf(d, d, ls);
    }
#pragma unroll
    for (int off = 16; off; off >>= 1) ls += __shfl_down_sync(0xffffffffu, ls, off);
    if ((tid & 31) == 0) sred[tid >> 5] = ls;
    __syncthreads();
    if (tid == 0) {
        float s = 0.f;
#pragma unroll
        for (int w = 0; w < 32; ++w) s += sred[w];
        g_lp[blockIdx.x] = s;
    }
}

// kD2: deterministic final loss reduction -> out[0]
__global__ void __launch_bounds__(128) kD2(float* __restrict__ out) {
    __shared__ float sred[4];
    const int tid = threadIdx.x;
    float s = g_lp[tid];
#pragma unroll
    for (int off = 16; off; off >>= 1) s += __shfl_down_sync(0xffffffffu, s, off);
    if ((tid & 31) == 0) sred[tid >> 5] = s;
    __syncthreads();
    if (tid == 0) {
        float t = 0.f;
#pragma unroll
        for (int w = 0; w < 4; ++w) t += sred[w];
        out[0] = t * (0.25f / 3276800.0f);
    }
}

// ---------------------------------------------------------------------------
// kE: gather codes, trans 1x1 (f32x2 s-pairs, weights from global), pose head.
// grid=1024, block=512.  smem floats: zr[3328] lat[2400] = 22912 B -> 4 CTAs/SM
// ---------------------------------------------------------------------------
#define SMEM_E_FLOATS (3328 + 2400)
#define KP_OFF (1 + 1228800)
__global__ void __launch_bounds__(512) kE(const float* __restrict__ codebook,
                                          const float* __restrict__ tw,
                                          const float* __restrict__ tb,
                                          const float* __restrict__ w1,
                                          const float* __restrict__ b1,
                                          const float* __restrict__ w2,
                                          const float* __restrict__ b2,
                                          float* __restrict__ out) {
    extern __shared__ float sm[];
    float* zr  = sm;            // 128 x 26 (col 25 = 0 pad)
    float* lat = zr + 3328;     // 96 x 25
    __shared__ float part[512];
    __shared__ float hid[32];
    const int bb = blockIdx.x;
    const int tid = threadIdx.x;

    for (int el = tid; el < 3328; el += 512) {
        int i = el / 26, k = el % 26;
        float v = 0.f;
        if (k < 25) {
            int ci = g_ind[bb * 128 + i];
            v = codebook[ci * 25 + k];
        }
        zr[el] = v;
    }
    __syncthreads();

    // trans 1x1: 96 oc x 13 s-pairs = 1248 items; packed FFMA2, aligned LDS.64
    for (int item = tid; item < 1248; item += 512) {
        const int oc = item / 13;
        const int s = (item % 13) * 2;
        ull acc = f2pk(0.f, 0.f);
#pragma unroll 4
        for (int i = 0; i < 128; ++i) {
            ull w = f2dup(__ldg(tw + i * 96 + oc));
            ull z = *(const ull*)(zr + i * 26 + s);
            acc = f2fma(w, z, acc);
        }
        float lo, hi; f2un(acc, lo, hi);
        const float bo = tb[oc];
        const float v0 = lo + bo;
        lat[oc * 25 + s] = v0;
        g_lat[bb * 2400 + oc * 25 + s] = v0;
        if (s + 1 < 25) {
            const float v1 = hi + bo;
            lat[oc * 25 + s + 1] = v1;
            g_lat[bb * 2400 + oc * 25 + s + 1] = v1;
        }
    }
    __syncthreads();

    // pose head
    const int warp = tid >> 5, lane = tid & 31;
    float a = 0.f;
    const int fbeg = warp * 150, fend = fbeg + 150;
    for (int f = fbeg; f < fend; ++f) a = fmaf(lat[f], w1[f * 32 + lane], a);
    part[warp * 32 + lane] = a;
    __syncthreads();
    if (tid < 32) {
        float s = b1[tid];
#pragma unroll
        for (int w = 0; w < 16; ++w) s += part[w * 32 + tid];
        hid[tid] = fmaxf(s, 0.f);
    }
    __syncthreads();
    if (tid < 36) {
        float acc = b2[tid];
#pragma unroll
        for (int h = 0; h < 32; ++h) acc = fmaf(hid[h], w2[h * 36 + tid], acc);
        out[KP_OFF + bb * 36 + tid] = acc;
    }
}

// ---------------------------------------------------------------------------
// kF: unpool2 + dec1 + relu + unpool1 + dec2.  grid=1024, block=800.
// smem floats: u2p[13824] u1[12800] = 26624 (106496 B) -> 2 CTAs/SM.
// Weights (dw1, dw2) read straight from global/L1.
// ---------------------------------------------------------------------------
#define SMEM_F_FLOATS (13824 + 12800)
__global__ void __launch_bounds__(800) kF(const float* __restrict__ dw1,
                                          const float* __restrict__ db1,
                                          const float* __restrict__ dw2,
                                          const float* __restrict__ db2,
                                          float* __restrict__ out) {
    extern __shared__ float sm[];
    float* u2p = sm;             // 96 x 12 x 12
    float* u1  = u2p + 13824;    // 32 x 20 x 20
    __shared__ float b1s[32];
    __shared__ float b2s[3];
    const int bb = blockIdx.x;
    const int tid = threadIdx.x;

    for (int i = tid; i < 13824; i += 800) u2p[i] = 0.f;
    for (int i = tid; i < 12800; i += 800) u1[i] = 0.f;
    if (tid < 32) b1s[tid] = db1[tid];
    if (tid < 3) b2s[tid] = db2[tid];
    __syncthreads();

    for (int el = tid; el < 2400; el += 800) {
        int c = el / 25, s = el % 25, py = s / 5, px = s % 5;
        float v = g_lat[bb * 2400 + el];
        int ii = g_i2[bb * 2400 + el];
        u2p[c * 144 + (2 * py + (ii >> 1) + 1) * 12 + (2 * px + (ii & 1) + 1)] = v;
    }
    __syncthreads();

    // dec1: 800 items, exactly 1 per thread; relu; unpool1 scatter
    {
        const int p = tid;
        const int oc = p / 25;
        const int pr = p % 25;
        const int py = pr / 5, px = pr % 5;
        ull acc0, acc1;
        conv3x3_patch12<96>(u2p + (2 * py) * 12 + 2 * px, dw1 + oc * 864, b1s[oc], acc0, acc1);
        float a[2][2];
        f2un(acc0, a[0][0], a[0][1]);
        f2un(acc1, a[1][0], a[1][1]);
#pragma unroll
        for (int dy = 0; dy < 2; ++dy)
#pragma unroll
            for (int dx = 0; dx < 2; ++dx) {
                const int y = 2 * py + dy, x = 2 * px + dx;
                float v = fmaxf(a[dy][dx], 0.f);
                int ii = g_i1[bb * 3200 + oc * 100 + y * 10 + x];
                u1[oc * 400 + (2 * y + (ii >> 1)) * 20 + (2 * x + (ii & 1))] = v;
            }
    }
    __syncthreads();

    // dec2 conv (32->3, 20x20, pad1), weights via L1
    for (int o = tid; o < 1200; o += 800) {
        const int oc = o / 400;
        const int r = o % 400;
        const int y = r / 20, x = r % 20;
        float acc = b2s[oc];
        for (int ic = 0; ic < 32; ++ic) {
            const float* wp = dw2 + (oc * 32 + ic) * 9;
            const float* up = u1 + ic * 400;
#pragma unroll
            for (int kh = 0; kh < 3; ++kh) {
                const int yy = y + kh - 1;
                if ((unsigned)yy < 20u) {
#pragma unroll
                    for (int kw = 0; kw < 3; ++kw) {
                        const int xx = x + kw - 1;
                        if ((unsigned)xx < 20u)
                            acc = fmaf(__ldg(wp + kh * 3 + kw), up[yy * 20 + xx], acc);
                    }
                }
            }
        }
        out[1 + bb * 1200 + o] = acc;
    }
}

// ---------------------------------------------------------------------------
extern "C" void kernel_launch(void* const* d_in, const int* in_sizes, int n_in,
                              void* d_out, int out_size) {
    const float* x    = (const float*)d_in[0];
    const float* e1w  = (const float*)d_in[1];
    const float* e1b  = (const float*)d_in[2];
    const float* e2w  = (const float*)d_in[3];
    const float* e2b  = (const float*)d_in[4];
    const float* prew = (const float*)d_in[5];
    const float* preb = (const float*)d_in[6];
    const float* cbk  = (const float*)d_in[7];
    const float* trw  = (const float*)d_in[8];
    const float* trb  = (const float*)d_in[9];
    const float* d1w  = (const float*)d_in[10];
    const float* d1b  = (const float*)d_in[11];
    const float* d2w  = (const float*)d_in[12];
    const float* d2b  = (const float*)d_in[13];
    const float* hw1  = (const float*)d_in[14];
    const float* hb1  = (const float*)d_in[15];
    const float* hw2  = (const float*)d_in[16];
    const float* hb2  = (const float*)d_in[17];
    float* out = (float*)d_out;

    cudaFuncSetAttribute(kB, cudaFuncAttributeMaxDynamicSharedMemorySize, SMEM_B_FLOATS * 4);
    cudaFuncSetAttribute(kD, cudaFuncAttributeMaxDynamicSharedMemorySize, SMEM_D_FLOATS * 4);
    cudaFuncSetAttribute(kE, cudaFuncAttributeMaxDynamicSharedMemorySize, SMEM_E_FLOATS * 4);
    cudaFuncSetAttribute(kF, cudaFuncAttributeMaxDynamicSharedMemorySize, SMEM_F_FLOATS * 4);

    kA<<<NB, 256>>>(x, e1w, e1b);
    kB<<<NB, 800, SMEM_B_FLOATS * 4>>>(e2w, e2b, prew, preb);
    kD<<<128, 1024, SMEM_D_FLOATS * 4>>>(cbk);
    kD2<<<1, 128>>>(out);
    kE<<<NB, 512, SMEM_E_FLOATS * 4>>>(cbk, trw, trb, hw1, hb1, hw2, hb2, out);
    kF<<<NB, 800, SMEM_F_FLOATS * 4>>>(d1w, d1b, d2w, d2b, out);
}

// round 9
// speedup vs baseline: 1.6049x; 1.6049x over previous
#include <cuda_runtime.h>
#include <cstdint>

// ---------------------------------------------------------------------------
// EfficientFi VQ-VAE forward, B=1024.  Round 9: row-based convs (broadcast
// input LDS, transposed weights), 2-image kB, ic-split kF. kA/kD/kE as R6.
// ---------------------------------------------------------------------------

#define NB 1024
typedef unsigned long long ull;

__device__ float         g_p1[NB * 3200];
__device__ unsigned char g_i1[NB * 3200];
__device__ float         g_vq[NB * 3200];
__device__ unsigned char g_i2[NB * 2400];
__device__ int           g_ind[NB * 128];
__device__ float         g_lat[NB * 2400];
__device__ float         g_lp[128];
__device__ float         g_w2t[27648];   // enc2 weights transposed [(ic*9+k)][96]
__device__ float         g_w1t[27648];   // dec1 weights transposed [(ic*9+k)][32]

// ---------------- f32x2 packed helpers (sm_103a) ----------------
static __device__ __forceinline__ ull f2pk(float a, float b) {
    ull r; asm("mov.b64 %0, {%1, %2};" : "=l"(r) : "f"(a), "f"(b)); return r;
}
static __device__ __forceinline__ void f2un(ull v, float& lo, float& hi) {
    asm("mov.b64 {%0, %1}, %2;" : "=f"(lo), "=f"(hi) : "l"(v));
}
static __device__ __forceinline__ ull f2dup(float a) { return f2pk(a, a); }
static __device__ __forceinline__ ull f2mul(ull a, ull b) {
    ull d; asm("mul.rn.f32x2 %0, %1, %2;" : "=l"(d) : "l"(a), "l"(b)); return d;
}
static __device__ __forceinline__ ull f2fma(ull a, ull b, ull c) {
    ull d; asm("fma.rn.f32x2 %0, %1, %2, %3;" : "=l"(d) : "l"(a), "l"(b), "l"(c)); return d;
}
static __device__ __forceinline__ ull f2add(ull a, ull b) {
    ull d; asm("add.rn.f32x2 %0, %1, %2;" : "=l"(d) : "l"(a), "l"(b)); return d;
}
static __device__ __forceinline__ float f2sum(ull v) {
    float lo, hi; f2un(v, lo, hi); return lo + hi;
}
static __device__ __forceinline__ ull f2mid(ull a, ull b) {
    float alo, ahi, blo, bhi; f2un(a, alo, ahi); f2un(b, blo, bhi);
    return f2pk(ahi, blo);
}

// one padded row (12 floats): 6 pairs + 5 mids
struct Row { ull P[6]; ull M[5]; };
static __device__ __forceinline__ void load_row(const float* __restrict__ rp, Row& R) {
    ulonglong2 q0 = *(const ulonglong2*)(rp);
    ulonglong2 q1 = *(const ulonglong2*)(rp + 4);
    ulonglong2 q2 = *(const ulonglong2*)(rp + 8);
    R.P[0] = q0.x; R.P[1] = q0.y; R.P[2] = q1.x; R.P[3] = q1.y; R.P[4] = q2.x; R.P[5] = q2.y;
#pragma unroll
    for (int k = 0; k < 5; ++k) R.M[k] = f2mid(R.P[k], R.P[k + 1]);
}
// apply one input row as conv w-row (wa,wb,wc) to 5 packed accumulators
static __device__ __forceinline__ void apply_row(const Row& R, ull wa, ull wb, ull wc, ull* acc) {
#pragma unroll
    for (int k = 0; k < 5; ++k) {
        acc[k] = f2fma(wa, R.P[k], acc[k]);
        acc[k] = f2fma(wb, R.M[k], acc[k]);
        acc[k] = f2fma(wc, R.P[k + 1], acc[k]);
    }
}

static __device__ __forceinline__ void pool_epi(ull r0, ull r1, float& best, int& bi) {
    float a00, a01, a10, a11;
    f2un(r0, a00, a01); f2un(r1, a10, a11);
    float v00 = fmaxf(a00, 0.f), v01 = fmaxf(a01, 0.f);
    float v10 = fmaxf(a10, 0.f), v11 = fmaxf(a11, 0.f);
    best = v00; bi = 0;
    if (v01 > best) { best = v01; bi = 1; }
    if (v10 > best) { best = v10; bi = 2; }
    if (v11 > best) { best = v11; bi = 3; }
}

// ---------------------------------------------------------------------------
// kT: one-shot weight transposer.  grid=108, block=512.
// ---------------------------------------------------------------------------
__global__ void __launch_bounds__(512) kT(const float* __restrict__ e2w,
                                          const float* __restrict__ d1w) {
    int i = blockIdx.x * 512 + threadIdx.x;
    if (i < 27648) {
        int kidx = i / 96, oc = i % 96;
        g_w2t[i] = e2w[oc * 288 + kidx];
    } else if (i < 55296) {
        int j = i - 27648;
        int kidx = j / 32, oc = j % 32;
        g_w1t[j] = d1w[oc * 864 + kidx];
    }
}

// ---------------------------------------------------------------------------
// kA: conv1 + relu + pool1.  grid=1024, block=256.  (R6 verbatim)
// ---------------------------------------------------------------------------
__global__ void __launch_bounds__(256) kA(const float* __restrict__ x,
                                          const float* __restrict__ w,
                                          const float* __restrict__ bias) {
    __shared__ float xp[3 * 484];
    __shared__ float ws[864];
    __shared__ float bs[32];
    const int bb = blockIdx.x;
    const int tid = threadIdx.x;

    for (int i = tid; i < 3 * 484; i += 256) xp[i] = 0.f;
    __syncthreads();
    for (int i = tid; i < 1200; i += 256) {
        int c = i / 400, r = i % 400, y = r / 20, xx = r % 20;
        xp[c * 484 + (y + 1) * 22 + (xx + 1)] = x[bb * 1200 + i];
    }
    for (int i = tid; i < 864; i += 256) ws[i] = w[i];
    if (tid < 32) bs[tid] = bias[tid];
    __syncthreads();

    for (int cell = tid; cell < 3200; cell += 256) {
        const int oc = cell / 100;
        const int r = cell % 100;
        const int py = r / 10, px = r % 10;
        float acc[2][2];
        acc[0][0] = acc[0][1] = acc[1][0] = acc[1][1] = bs[oc];
#pragma unroll
        for (int c = 0; c < 3; ++c) {
            const int base = c * 484 + (2 * py) * 22 + 2 * px;
            float in[4][4];
#pragma unroll
            for (int rr = 0; rr < 4; ++rr)
#pragma unroll
                for (int cc = 0; cc < 4; ++cc) in[rr][cc] = xp[base + rr * 22 + cc];
            const float* wp = ws + (oc * 3 + c) * 9;
#pragma unroll
            for (int kh = 0; kh < 3; ++kh)
#pragma unroll
                for (int kw = 0; kw < 3; ++kw) {
                    const float wv = wp[kh * 3 + kw];
#pragma unroll
                    for (int dy = 0; dy < 2; ++dy)
#pragma unroll
                        for (int dx = 0; dx < 2; ++dx)
                            acc[dy][dx] = fmaf(wv, in[dy + kh][dx + kw], acc[dy][dx]);
                }
        }
        float best = -1.f;
        int bi = 0;
#pragma unroll
        for (int dy = 0; dy < 2; ++dy)
#pragma unroll
            for (int dx = 0; dx < 2; ++dx) {
                float v = fmaxf(acc[dy][dx], 0.f);
                int ii = dy * 2 + dx;
                if (v > best) { best = v; bi = ii; }
            }
        g_p1[bb * 3200 + cell] = best;
        g_i1[bb * 3200 + cell] = (unsigned char)bi;
    }
}

// ---------------------------------------------------------------------------
// kB: conv2+relu+pool2 (row-based) + pre 1x1.  grid=512 (2 images/CTA), block=480.
// smem floats: p1p[2][4608] w2t[27648] b2s[96] zs[2][2400] pws[12288] pbs[128]
//            = 54176 (216704 B)
// ---------------------------------------------------------------------------
#define SMEM_B_FLOATS (2 * 4608 + 27648 + 96 + 2 * 2400 + 12288 + 128)
__global__ void __launch_bounds__(480) kB(const float* __restrict__ b2,
                                          const float* __restrict__ pw,
                                          const float* __restrict__ pb) {
    extern __shared__ float sm[];
    float* p1p = sm;              // 2 x (32 x 12 x 12)
    float* w2t = p1p + 9216;      // 27648, [(ic*9+k)][96]
    float* b2s = w2t + 27648;     // 96
    float* zs  = b2s + 96;        // 2 x (96 x 25)
    float* pws = zs + 4800;       // 12288
    float* pbs = pws + 12288;     // 128
    const int bb = blockIdx.x;
    const int tid = threadIdx.x;

    for (int i = tid; i < 9216; i += 480) p1p[i] = 0.f;
    __syncthreads();
    for (int i = tid; i < 6400; i += 480) {
        int img = i / 3200, r0 = i % 3200;
        int c = r0 / 100, r = r0 % 100, y = r / 10, xx = r % 10;
        p1p[img * 4608 + c * 144 + (y + 1) * 12 + (xx + 1)] = g_p1[(2 * bb + img) * 3200 + r0];
    }
    {
        const float4* s4 = (const float4*)g_w2t;
        float4* d4 = (float4*)w2t;
        for (int i = tid; i < 6912; i += 480) d4[i] = s4[i];
    }
    if (tid < 96) b2s[tid] = b2[tid];
    {
        const float4* s4 = (const float4*)pw;
        float4* d4 = (float4*)pws;
        for (int i = tid; i < 3072; i += 480) d4[i] = s4[i];
    }
    if (tid < 128) pbs[tid] = pb[tid];
    __syncthreads();

    // row-based conv2+pool: item = prow*96 + oc (warp = 32 oc, same prow)
    const int oc = tid % 96 % 96;
    const int item_oc = tid % 96;
    const int prow = tid / 96;            // 0..4 (480 = 5*96)
    (void)oc;
#pragma unroll
    for (int img = 0; img < 2; ++img) {
        const float* tile = p1p + img * 4608 + (2 * prow) * 12;
        float* zsi = zs + img * 2400;
        ull acc0[5], acc1[5];
        {
            ull b = f2dup(b2s[item_oc]);
#pragma unroll
            for (int k = 0; k < 5; ++k) { acc0[k] = b; acc1[k] = b; }
        }
        for (int ic = 0; ic < 32; ++ic) {
            const float* wq = w2t + ic * 9 * 96 + item_oc;
            ull w0 = f2dup(wq[0]),     w1 = f2dup(wq[96]),    w2 = f2dup(wq[192]);
            ull w3 = f2dup(wq[288]),   w4 = f2dup(wq[384]),   w5 = f2dup(wq[480]);
            ull w6 = f2dup(wq[576]),   w7 = f2dup(wq[672]),   w8 = f2dup(wq[768]);
            const float* cp = tile + ic * 144;
            Row R;
            load_row(cp, R);            // padded row 2*prow   (conv row y0, w-row 0)
            apply_row(R, w0, w1, w2, acc0);
            load_row(cp + 12, R);       // row 2*prow+1
            apply_row(R, w3, w4, w5, acc0);
            apply_row(R, w0, w1, w2, acc1);
            load_row(cp + 24, R);       // row 2*prow+2
            apply_row(R, w6, w7, w8, acc0);
            apply_row(R, w3, w4, w5, acc1);
            load_row(cp + 36, R);       // row 2*prow+3
            apply_row(R, w6, w7, w8, acc1);
        }
#pragma unroll
        for (int k = 0; k < 5; ++k) {
            float best; int bi;
            pool_epi(acc0[k], acc1[k], best, bi);
            const int cell = item_oc * 25 + prow * 5 + k;
            zsi[cell] = best;
            g_i2[(2 * bb + img) * 2400 + cell] = (unsigned char)bi;
        }
    }
    __syncthreads();

    // pre 1x1 — chain byte-identical to R6 (feeds VQ argmin!)
    for (int o = tid; o < 6400; o += 480) {
        const int img = o / 3200, oo = o % 3200;
        const int e = oo / 25, s = oo % 25;
        const float* wp = pws + e * 96;
        const float* zsi = zs + img * 2400;
        float a0 = 0.f, a1 = 0.f, a2 = 0.f, a3 = 0.f;
#pragma unroll 4
        for (int c = 0; c < 96; c += 4) {
            a0 = fmaf(wp[c + 0], zsi[(c + 0) * 25 + s], a0);
            a1 = fmaf(wp[c + 1], zsi[(c + 1) * 25 + s], a1);
            a2 = fmaf(wp[c + 2], zsi[(c + 2) * 25 + s], a2);
            a3 = fmaf(wp[c + 3], zsi[(c + 3) * 25 + s], a3);
        }
        g_vq[(2 * bb + img) * 3200 + oo] = (a0 + a1) + (a2 + a3) + pbs[e];
    }
}

// ---------------------------------------------------------------------------
// kD: VQ argmin. grid=128, block=1024. smem 114688 B. (R6 verbatim)
// ---------------------------------------------------------------------------
#define SMEM_D_FLOATS (1024 * 28)
__global__ void __launch_bounds__(1024) kD(const float* __restrict__ codebook) {
    extern __shared__ float cb[];
    __shared__ float sred[32];
    const int tid = threadIdx.x;

    if (tid < 1024) {
        const int j = tid;
        float nrm = 0.f;
#pragma unroll
        for (int k = 0; k < 25; ++k) {
            float v = codebook[j * 25 + k];
            cb[j * 28 + k] = v;
            nrm = fmaf(v, v, nrm);
        }
        cb[j * 28 + 25] = 0.5f * nrm;
        cb[j * 28 + 26] = 0.f;
        cb[j * 28 + 27] = 0.f;
    }
    __syncthreads();

    const int t = blockIdx.x * 1024 + tid;
    ull fp[14];
    {
        const float* fv = g_vq + t * 25;
#pragma unroll
        for (int i = 0; i < 12; ++i) fp[i] = f2pk(fv[2 * i], fv[2 * i + 1]);
        fp[12] = f2pk(fv[24], -1.0f);
        fp[13] = f2pk(0.f, 0.f);
    }

    float best = -3.402823e38f;
    int bi = 0;
#pragma unroll 2
    for (int j = 0; j < 1024; ++j) {
        const ulonglong2* row = reinterpret_cast<const ulonglong2*>(cb + j * 28);
        ulonglong2 v0 = row[0], v1 = row[1], v2 = row[2], v3 = row[3];
        ulonglong2 v4 = row[4], v5 = row[5], v6 = row[6];
        ull a = f2mul(fp[0], v0.x);
        ull c = f2mul(fp[1], v0.y);
        a = f2fma(fp[2], v1.x, a);  c = f2fma(fp[3], v1.y, c);
        a = f2fma(fp[4], v2.x, a);  c = f2fma(fp[5], v2.y, c);
        a = f2fma(fp[6], v3.x, a);  c = f2fma(fp[7], v3.y, c);
        a = f2fma(fp[8], v4.x, a);  c = f2fma(fp[9], v4.y, c);
        a = f2fma(fp[10], v5.x, a); c = f2fma(fp[11], v5.y, c);
        a = f2fma(fp[12], v6.x, a); c = f2fma(fp[13], v6.y, c);
        float sc = f2sum(f2add(a, c));
        if (sc > best) { best = sc; bi = j; }  // strict > == first-argmin
    }
    g_ind[t] = bi;

    float ls = 0.f;
    const float* rr = cb + bi * 28;
#pragma unroll
    for (int i = 0; i < 12; ++i) {
        float lo, hi; f2un(fp[i], lo, hi);
        float d0 = rr[2 * i] - lo;     ls = fmaf(d0, d0, ls);
        float d1 = rr[2 * i + 1] - hi; ls = fmaf(d1, d1, ls);
    }
    {
        float lo, hi; f2un(fp[12], lo, hi);
        float d = rr[24] - lo; ls = fmaf(d, d, ls);
    }
#pragma unroll
    for (int off = 16; off; off >>= 1) ls += __shfl_down_sync(0xffffffffu, ls, off);
    if ((tid & 31) == 0) sred[tid >> 5] = ls;
    __syncthreads();
    if (tid == 0) {
        float s = 0.f;
#pragma unroll
        for (int w = 0; w < 32; ++w) s += sred[w];
        g_lp[blockIdx.x] = s;
    }
}

__global__ void __launch_bounds__(128) kD2(float* __restrict__ out) {
    __shared__ float sred[4];
    const int tid = threadIdx.x;
    float s = g_lp[tid];
#pragma unroll
    for (int off = 16; off; off >>= 1) s += __shfl_down_sync(0xffffffffu, s, off);
    if ((tid & 31) == 0) sred[tid >> 5] = s;
    __syncthreads();
    if (tid == 0) {
        float t = 0.f;
#pragma unroll
        for (int w = 0; w < 4; ++w) t += sred[w];
        out[0] = t * (0.25f / 3276800.0f);
    }
}

// ---------------------------------------------------------------------------
// kE: gather codes, trans 1x1 (f32x2 s-pairs), pose head.  (R6 verbatim)
// grid=1024, block=512. smem floats: zr[3328] tws[12288] lat[2400]
// ---------------------------------------------------------------------------
#define SMEM_E_FLOATS (3328 + 12288 + 2400)
#define KP_OFF (1 + 1228800)
__global__ void __launch_bounds__(512) kE(const float* __restrict__ codebook,
                                          const float* __restrict__ tw,
                                          const float* __restrict__ tb,
                                          const float* __restrict__ w1,
                                          const float* __restrict__ b1,
                                          const float* __restrict__ w2,
                                          const float* __restrict__ b2,
                                          float* __restrict__ out) {
    extern __shared__ float sm[];
    float* zr  = sm;            // 128 x 26 (col 25 = 0 pad)
    float* tws = zr + 3328;     // 12288
    float* lat = tws + 12288;   // 96 x 25
    __shared__ float part[512];
    __shared__ float hid[32];
    const int bb = blockIdx.x;
    const int tid = threadIdx.x;

    {
        const float4* s4 = (const float4*)tw;
        float4* d4 = (float4*)tws;
        for (int i = tid; i < 3072; i += 512) d4[i] = s4[i];
    }
    for (int el = tid; el < 3328; el += 512) {
        int i = el / 26, k = el % 26;
        float v = 0.f;
        if (k < 25) {
            int ci = g_ind[bb * 128 + i];
            v = codebook[ci * 25 + k];
        }
        zr[el] = v;
    }
    __syncthreads();

    for (int item = tid; item < 1248; item += 512) {
        const int oc = item / 13;
        const int s = (item % 13) * 2;
        ull acc = f2pk(0.f, 0.f);
#pragma unroll 4
        for (int i = 0; i < 128; ++i) {
            ull w = f2dup(tws[i * 96 + oc]);
            ull z = *(const ull*)(zr + i * 26 + s);
            acc = f2fma(w, z, acc);
        }
        float lo, hi; f2un(acc, lo, hi);
        const float bo = tb[oc];
        const float v0 = lo + bo;
        lat[oc * 25 + s] = v0;
        g_lat[bb * 2400 + oc * 25 + s] = v0;
        if (s + 1 < 25) {
            const float v1 = hi + bo;
            lat[oc * 25 + s + 1] = v1;
            g_lat[bb * 2400 + oc * 25 + s + 1] = v1;
        }
    }
    __syncthreads();

    const int warp = tid >> 5, lane = tid & 31;
    float a = 0.f;
    const int fbeg = warp * 150, fend = fbeg + 150;
    for (int f = fbeg; f < fend; ++f) a = fmaf(lat[f], w1[f * 32 + lane], a);
    part[warp * 32 + lane] = a;
    __syncthreads();
    if (tid < 32) {
        float s = b1[tid];
#pragma unroll
        for (int w = 0; w < 16; ++w) s += part[w * 32 + tid];
        hid[tid] = fmaxf(s, 0.f);
    }
    __syncthreads();
    if (tid < 36) {
        float acc = b2[tid];
#pragma unroll
        for (int h = 0; h < 32; ++h) acc = fmaf(hid[h], w2[h * 36 + tid], acc);
        out[KP_OFF + bb * 36 + tid] = acc;
    }
}

// ---------------------------------------------------------------------------
// kF: unpool2 + dec1 (row-based, ic-split partials) + relu + unpool1 + dec2.
// grid=1024, block=480.
// smem floats: u2p[13824] w1t[27648] union[12800] w2s[864] = 55136 (220544 B)
// union holds partials (4800 ull) during conv, then u1 (12800 fl).
// ---------------------------------------------------------------------------
#define SMEM_F_FLOATS (13824 + 27648 + 12800 + 864)
__global__ void __launch_bounds__(480) kF(const float* __restrict__ db1,
                                          const float* __restrict__ dw2,
                                          const float* __restrict__ db2,
                                          float* __restrict__ out) {
    extern __shared__ float sm[];
    float* u2p = sm;               // 96 x 12 x 12
    float* w1t = u2p + 13824;      // 27648, [(ic*9+k)][32]
    float* uni = w1t + 27648;      // 12800: partials then u1
    float* w2s = uni + 12800;      // 864
    ull*   part = (ull*)uni;       // 4800 ull used
    __shared__ float b1s[32];
    __shared__ float b2s[3];
    const int bb = blockIdx.x;
    const int tid = threadIdx.x;

    for (int i = tid; i < 13824; i += 480) u2p[i] = 0.f;
    if (tid < 32) b1s[tid] = db1[tid];
    if (tid < 3) b2s[tid] = db2[tid];
    {
        const float4* s4 = (const float4*)g_w1t;
        float4* d4 = (float4*)w1t;
        for (int i = tid; i < 6912; i += 480) d4[i] = s4[i];
    }
    {
        const float4* s4 = (const float4*)dw2;
        float4* d4 = (float4*)w2s;
        for (int i = tid; i < 216; i += 480) d4[i] = s4[i];
    }
    __syncthreads();

    for (int el = tid; el < 2400; el += 480) {
        int c = el / 25, s = el % 25, py = s / 5, px = s % 5;
        float v = g_lat[bb * 2400 + el];
        int ii = g_i2[bb * 2400 + el];
        u2p[c * 144 + (2 * py + (ii >> 1) + 1) * 12 + (2 * px + (ii & 1) + 1)] = v;
    }
    __syncthreads();

    // dec1 conv partials: item = (icg*5 + prow)*32 + oc ; 480 items, 1/thread.
    // (reassociation across icg is safe: dec1 feeds only continuous r_x)
    {
        const int wrp = tid / 32;        // 0..14
        const int icg = wrp / 5;         // 0..2
        const int prow = wrp % 5;        // 0..4
        const int oc = tid % 32;
        const float* tile = u2p + (2 * prow) * 12;
        ull acc0[5], acc1[5];
#pragma unroll
        for (int k = 0; k < 5; ++k) { acc0[k] = 0ull; acc1[k] = 0ull; }
        const int ic0 = icg * 32;
        for (int ic = ic0; ic < ic0 + 32; ++ic) {
            const float* wq = w1t + ic * 9 * 32 + oc;
            ull w0 = f2dup(wq[0]),   w1 = f2dup(wq[32]),  w2 = f2dup(wq[64]);
            ull w3 = f2dup(wq[96]),  w4 = f2dup(wq[128]), w5 = f2dup(wq[160]);
            ull w6 = f2dup(wq[192]), w7 = f2dup(wq[224]), w8 = f2dup(wq[256]);
            const float* cp = tile + ic * 144;
            Row R;
            load_row(cp, R);
            apply_row(R, w0, w1, w2, acc0);
            load_row(cp + 12, R);
            apply_row(R, w3, w4, w5, acc0);
            apply_row(R, w0, w1, w2, acc1);
            load_row(cp + 24, R);
            apply_row(R, w6, w7, w8, acc0);
            apply_row(R, w3, w4, w5, acc1);
            load_row(cp + 36, R);
            apply_row(R, w6, w7, w8, acc1);
        }
#pragma unroll
        for (int k = 0; k < 5; ++k) {
            part[(2 * k + 0) * 480 + tid] = acc0[k];
            part[(2 * k + 1) * 480 + tid] = acc1[k];
        }
    }
    __syncthreads();

    // combine partials into registers (160 threads: j = prow*32 + oc)
    ull vv[10];
    if (tid < 160) {
        const int oc = tid % 32;
        const ull bco = f2dup(b1s[oc]);
#pragma unroll
        for (int q = 0; q < 10; ++q) {
            ull p0 = part[q * 480 + 0 * 160 + tid];
            ull p1 = part[q * 480 + 1 * 160 + tid];
            ull p2 = part[q * 480 + 2 * 160 + tid];
            vv[q] = f2add(f2add(f2add(bco, p0), p1), p2);
        }
    }
    __syncthreads();
    for (int i = tid; i < 12800; i += 480) uni[i] = 0.f;   // uni becomes u1
    __syncthreads();
    if (tid < 160) {
        const int prow = tid / 32;
        const int oc = tid % 32;
#pragma unroll
        for (int k = 0; k < 5; ++k)
#pragma unroll
            for (int dy = 0; dy < 2; ++dy) {
                float lo, hi; f2un(vv[2 * k + dy], lo, hi);
                const int y = 2 * prow + dy;
#pragma unroll
                for (int dx = 0; dx < 2; ++dx) {
                    const int x = 2 * k + dx;
                    float v = fmaxf(dx == 0 ? lo : hi, 0.f);
                    int ii = g_i1[bb * 3200 + oc * 100 + y * 10 + x];
                    uni[oc * 400 + (2 * y + (ii >> 1)) * 20 + (2 * x + (ii & 1))] = v;
                }
            }
    }
    __syncthreads();

    // dec2 conv (32->3, 20x20, pad1) — chain identical to R6
    for (int o = tid; o < 1200; o += 480) {
        const int oc = o / 400;
        const int r = o % 400;
        const int y = r / 20, x = r % 20;
        float acc = b2s[oc];
        for (int ic = 0; ic < 32; ++ic) {
            const float* wp = w2s + (oc * 32 + ic) * 9;
            const float* up = uni + ic * 400;
#pragma unroll
            for (int kh = 0; kh < 3; ++kh) {
                const int yy = y + kh - 1;
                if ((unsigned)yy < 20u) {
#pragma unroll
                    for (int kw = 0; kw < 3; ++kw) {
                        const int xx = x + kw - 1;
                        if ((unsigned)xx < 20u)
                            acc = fmaf(wp[kh * 3 + kw], up[yy * 20 + xx], acc);
                    }
                }
            }
        }
        out[1 + bb * 1200 + o] = acc;
    }
}

// ---------------------------------------------------------------------------
extern "C" void kernel_launch(void* const* d_in, const int* in_sizes, int n_in,
                              void* d_out, int out_size) {
    const float* x    = (const float*)d_in[0];
    const float* e1w  = (const float*)d_in[1];
    const float* e1b  = (const float*)d_in[2];
    const float* e2w  = (const float*)d_in[3];
    const float* e2b  = (const float*)d_in[4];
    const float* prew = (const float*)d_in[5];
    const float* preb = (const float*)d_in[6];
    const float* cbk  = (const float*)d_in[7];
    const float* trw  = (const float*)d_in[8];
    const float* trb  = (const float*)d_in[9];
    const float* d1w  = (const float*)d_in[10];
    const float* d1b  = (const float*)d_in[11];
    const float* d2w  = (const float*)d_in[12];
    const float* d2b  = (const float*)d_in[13];
    const float* hw1  = (const float*)d_in[14];
    const float* hb1  = (const float*)d_in[15];
    const float* hw2  = (const float*)d_in[16];
    const float* hb2  = (const float*)d_in[17];
    float* out = (float*)d_out;

    cudaFuncSetAttribute(kB, cudaFuncAttributeMaxDynamicSharedMemorySize, SMEM_B_FLOATS * 4);
    cudaFuncSetAttribute(kD, cudaFuncAttributeMaxDynamicSharedMemorySize, SMEM_D_FLOATS * 4);
    cudaFuncSetAttribute(kE, cudaFuncAttributeMaxDynamicSharedMemorySize, SMEM_E_FLOATS * 4);
    cudaFuncSetAttribute(kF, cudaFuncAttributeMaxDynamicSharedMemorySize, SMEM_F_FLOATS * 4);

    kT<<<108, 512>>>(e2w, d1w);
    kA<<<NB, 256>>>(x, e1w, e1b);
    kB<<<512, 480, SMEM_B_FLOATS * 4>>>(e2b, prew, preb);
    kD<<<128, 1024, SMEM_D_FLOATS * 4>>>(cbk);
    kD2<<<1, 128>>>(out);
    kE<<<NB, 512, SMEM_E_FLOATS * 4>>>(cbk, trw, trb, hw1, hb1, hw2, hb2, out);
    kF<<<NB, 480, SMEM_F_FLOATS * 4>>>(d1b, d2w, d2b, out);
}

// round 10
// speedup vs baseline: 1.7939x; 1.1177x over previous
#include <cuda_runtime.h>
#include <cstdint>

// ---------------------------------------------------------------------------
// EfficientFi VQ-VAE forward, B=1024.  Round 10: R9 + 2-token kD.
// ---------------------------------------------------------------------------

#define NB 1024
typedef unsigned long long ull;

__device__ float         g_p1[NB * 3200];
__device__ unsigned char g_i1[NB * 3200];
__device__ float         g_vq[NB * 3200];
__device__ unsigned char g_i2[NB * 2400];
__device__ int           g_ind[NB * 128];
__device__ float         g_lat[NB * 2400];
__device__ float         g_lp[128];
__device__ float         g_w2t[27648];   // enc2 weights transposed [(ic*9+k)][96]
__device__ float         g_w1t[27648];   // dec1 weights transposed [(ic*9+k)][32]

// ---------------- f32x2 packed helpers (sm_103a) ----------------
static __device__ __forceinline__ ull f2pk(float a, float b) {
    ull r; asm("mov.b64 %0, {%1, %2};" : "=l"(r) : "f"(a), "f"(b)); return r;
}
static __device__ __forceinline__ void f2un(ull v, float& lo, float& hi) {
    asm("mov.b64 {%0, %1}, %2;" : "=f"(lo), "=f"(hi) : "l"(v));
}
static __device__ __forceinline__ ull f2dup(float a) { return f2pk(a, a); }
static __device__ __forceinline__ ull f2mul(ull a, ull b) {
    ull d; asm("mul.rn.f32x2 %0, %1, %2;" : "=l"(d) : "l"(a), "l"(b)); return d;
}
static __device__ __forceinline__ ull f2fma(ull a, ull b, ull c) {
    ull d; asm("fma.rn.f32x2 %0, %1, %2, %3;" : "=l"(d) : "l"(a), "l"(b), "l"(c)); return d;
}
static __device__ __forceinline__ ull f2add(ull a, ull b) {
    ull d; asm("add.rn.f32x2 %0, %1, %2;" : "=l"(d) : "l"(a), "l"(b)); return d;
}
static __device__ __forceinline__ float f2sum(ull v) {
    float lo, hi; f2un(v, lo, hi); return lo + hi;
}
static __device__ __forceinline__ ull f2mid(ull a, ull b) {
    float alo, ahi, blo, bhi; f2un(a, alo, ahi); f2un(b, blo, bhi);
    return f2pk(ahi, blo);
}

// one padded row (12 floats): 6 pairs + 5 mids
struct Row { ull P[6]; ull M[5]; };
static __device__ __forceinline__ void load_row(const float* __restrict__ rp, Row& R) {
    ulonglong2 q0 = *(const ulonglong2*)(rp);
    ulonglong2 q1 = *(const ulonglong2*)(rp + 4);
    ulonglong2 q2 = *(const ulonglong2*)(rp + 8);
    R.P[0] = q0.x; R.P[1] = q0.y; R.P[2] = q1.x; R.P[3] = q1.y; R.P[4] = q2.x; R.P[5] = q2.y;
#pragma unroll
    for (int k = 0; k < 5; ++k) R.M[k] = f2mid(R.P[k], R.P[k + 1]);
}
static __device__ __forceinline__ void apply_row(const Row& R, ull wa, ull wb, ull wc, ull* acc) {
#pragma unroll
    for (int k = 0; k < 5; ++k) {
        acc[k] = f2fma(wa, R.P[k], acc[k]);
        acc[k] = f2fma(wb, R.M[k], acc[k]);
        acc[k] = f2fma(wc, R.P[k + 1], acc[k]);
    }
}

static __device__ __forceinline__ void pool_epi(ull r0, ull r1, float& best, int& bi) {
    float a00, a01, a10, a11;
    f2un(r0, a00, a01); f2un(r1, a10, a11);
    float v00 = fmaxf(a00, 0.f), v01 = fmaxf(a01, 0.f);
    float v10 = fmaxf(a10, 0.f), v11 = fmaxf(a11, 0.f);
    best = v00; bi = 0;
    if (v01 > best) { best = v01; bi = 1; }
    if (v10 > best) { best = v10; bi = 2; }
    if (v11 > best) { best = v11; bi = 3; }
}

// ---------------------------------------------------------------------------
// kT: one-shot weight transposer.  grid=108, block=512.
// ---------------------------------------------------------------------------
__global__ void __launch_bounds__(512) kT(const float* __restrict__ e2w,
                                          const float* __restrict__ d1w) {
    int i = blockIdx.x * 512 + threadIdx.x;
    if (i < 27648) {
        int kidx = i / 96, oc = i % 96;
        g_w2t[i] = e2w[oc * 288 + kidx];
    } else if (i < 55296) {
        int j = i - 27648;
        int kidx = j / 32, oc = j % 32;
        g_w1t[j] = d1w[oc * 864 + kidx];
    }
}

// ---------------------------------------------------------------------------
// kA: conv1 + relu + pool1.  grid=1024, block=256.  (R6 verbatim)
// ---------------------------------------------------------------------------
__global__ void __launch_bounds__(256) kA(const float* __restrict__ x,
                                          const float* __restrict__ w,
                                          const float* __restrict__ bias) {
    __shared__ float xp[3 * 484];
    __shared__ float ws[864];
    __shared__ float bs[32];
    const int bb = blockIdx.x;
    const int tid = threadIdx.x;

    for (int i = tid; i < 3 * 484; i += 256) xp[i] = 0.f;
    __syncthreads();
    for (int i = tid; i < 1200; i += 256) {
        int c = i / 400, r = i % 400, y = r / 20, xx = r % 20;
        xp[c * 484 + (y + 1) * 22 + (xx + 1)] = x[bb * 1200 + i];
    }
    for (int i = tid; i < 864; i += 256) ws[i] = w[i];
    if (tid < 32) bs[tid] = bias[tid];
    __syncthreads();

    for (int cell = tid; cell < 3200; cell += 256) {
        const int oc = cell / 100;
        const int r = cell % 100;
        const int py = r / 10, px = r % 10;
        float acc[2][2];
        acc[0][0] = acc[0][1] = acc[1][0] = acc[1][1] = bs[oc];
#pragma unroll
        for (int c = 0; c < 3; ++c) {
            const int base = c * 484 + (2 * py) * 22 + 2 * px;
            float in[4][4];
#pragma unroll
            for (int rr = 0; rr < 4; ++rr)
#pragma unroll
                for (int cc = 0; cc < 4; ++cc) in[rr][cc] = xp[base + rr * 22 + cc];
            const float* wp = ws + (oc * 3 + c) * 9;
#pragma unroll
            for (int kh = 0; kh < 3; ++kh)
#pragma unroll
                for (int kw = 0; kw < 3; ++kw) {
                    const float wv = wp[kh * 3 + kw];
#pragma unroll
                    for (int dy = 0; dy < 2; ++dy)
#pragma unroll
                        for (int dx = 0; dx < 2; ++dx)
                            acc[dy][dx] = fmaf(wv, in[dy + kh][dx + kw], acc[dy][dx]);
                }
        }
        float best = -1.f;
        int bi = 0;
#pragma unroll
        for (int dy = 0; dy < 2; ++dy)
#pragma unroll
            for (int dx = 0; dx < 2; ++dx) {
                float v = fmaxf(acc[dy][dx], 0.f);
                int ii = dy * 2 + dx;
                if (v > best) { best = v; bi = ii; }
            }
        g_p1[bb * 3200 + cell] = best;
        g_i1[bb * 3200 + cell] = (unsigned char)bi;
    }
}

// ---------------------------------------------------------------------------
// kB: conv2+relu+pool2 (row-based) + pre 1x1.  grid=512 (2 images/CTA), block=480.
// ---------------------------------------------------------------------------
#define SMEM_B_FLOATS (2 * 4608 + 27648 + 96 + 2 * 2400 + 12288 + 128)
__global__ void __launch_bounds__(480) kB(const float* __restrict__ b2,
                                          const float* __restrict__ pw,
                                          const float* __restrict__ pb) {
    extern __shared__ float sm[];
    float* p1p = sm;              // 2 x (32 x 12 x 12)
    float* w2t = p1p + 9216;      // 27648, [(ic*9+k)][96]
    float* b2s = w2t + 27648;     // 96
    float* zs  = b2s + 96;        // 2 x (96 x 25)
    float* pws = zs + 4800;       // 12288
    float* pbs = pws + 12288;     // 128
    const int bb = blockIdx.x;
    const int tid = threadIdx.x;

    for (int i = tid; i < 9216; i += 480) p1p[i] = 0.f;
    __syncthreads();
    for (int i = tid; i < 6400; i += 480) {
        int img = i / 3200, r0 = i % 3200;
        int c = r0 / 100, r = r0 % 100, y = r / 10, xx = r % 10;
        p1p[img * 4608 + c * 144 + (y + 1) * 12 + (xx + 1)] = g_p1[(2 * bb + img) * 3200 + r0];
    }
    {
        const float4* s4 = (const float4*)g_w2t;
        float4* d4 = (float4*)w2t;
        for (int i = tid; i < 6912; i += 480) d4[i] = s4[i];
    }
    if (tid < 96) b2s[tid] = b2[tid];
    {
        const float4* s4 = (const float4*)pw;
        float4* d4 = (float4*)pws;
        for (int i = tid; i < 3072; i += 480) d4[i] = s4[i];
    }
    if (tid < 128) pbs[tid] = pb[tid];
    __syncthreads();

    const int item_oc = tid % 96;
    const int prow = tid / 96;            // 0..4 (480 = 5*96)
#pragma unroll
    for (int img = 0; img < 2; ++img) {
        const float* tile = p1p + img * 4608 + (2 * prow) * 12;
        float* zsi = zs + img * 2400;
        ull acc0[5], acc1[5];
        {
            ull b = f2dup(b2s[item_oc]);
#pragma unroll
            for (int k = 0; k < 5; ++k) { acc0[k] = b; acc1[k] = b; }
        }
        for (int ic = 0; ic < 32; ++ic) {
            const float* wq = w2t + ic * 9 * 96 + item_oc;
            ull w0 = f2dup(wq[0]),     w1 = f2dup(wq[96]),    w2 = f2dup(wq[192]);
            ull w3 = f2dup(wq[288]),   w4 = f2dup(wq[384]),   w5 = f2dup(wq[480]);
            ull w6 = f2dup(wq[576]),   w7 = f2dup(wq[672]),   w8 = f2dup(wq[768]);
            const float* cp = tile + ic * 144;
            Row R;
            load_row(cp, R);
            apply_row(R, w0, w1, w2, acc0);
            load_row(cp + 12, R);
            apply_row(R, w3, w4, w5, acc0);
            apply_row(R, w0, w1, w2, acc1);
            load_row(cp + 24, R);
            apply_row(R, w6, w7, w8, acc0);
            apply_row(R, w3, w4, w5, acc1);
            load_row(cp + 36, R);
            apply_row(R, w6, w7, w8, acc1);
        }
#pragma unroll
        for (int k = 0; k < 5; ++k) {
            float best; int bi;
            pool_epi(acc0[k], acc1[k], best, bi);
            const int cell = item_oc * 25 + prow * 5 + k;
            zsi[cell] = best;
            g_i2[(2 * bb + img) * 2400 + cell] = (unsigned char)bi;
        }
    }
    __syncthreads();

    // pre 1x1 — chain byte-identical to R6 (feeds VQ argmin!)
    for (int o = tid; o < 6400; o += 480) {
        const int img = o / 3200, oo = o % 3200;
        const int e = oo / 25, s = oo % 25;
        const float* wp = pws + e * 96;
        const float* zsi = zs + img * 2400;
        float a0 = 0.f, a1 = 0.f, a2 = 0.f, a3 = 0.f;
#pragma unroll 4
        for (int c = 0; c < 96; c += 4) {
            a0 = fmaf(wp[c + 0], zsi[(c + 0) * 25 + s], a0);
            a1 = fmaf(wp[c + 1], zsi[(c + 1) * 25 + s], a1);
            a2 = fmaf(wp[c + 2], zsi[(c + 2) * 25 + s], a2);
            a3 = fmaf(wp[c + 3], zsi[(c + 3) * 25 + s], a3);
        }
        g_vq[(2 * bb + img) * 3200 + oo] = (a0 + a1) + (a2 + a3) + pbs[e];
    }
}

// ---------------------------------------------------------------------------
// kD: VQ argmin, 2 tokens/thread. grid=128, block=512. smem 114688 B.
// Scoring chain identical to the R5-passing 2-token version.
// ---------------------------------------------------------------------------
#define SMEM_D_FLOATS (1024 * 28)
__global__ void __launch_bounds__(512) kD(const float* __restrict__ codebook) {
    extern __shared__ float cb[];
    __shared__ float sred[16];
    const int tid = threadIdx.x;

    for (int j = tid; j < 1024; j += 512) {
        float nrm = 0.f;
#pragma unroll
        for (int k = 0; k < 25; ++k) {
            float v = codebook[j * 25 + k];
            cb[j * 28 + k] = v;
            nrm = fmaf(v, v, nrm);
        }
        cb[j * 28 + 25] = 0.5f * nrm;
        cb[j * 28 + 26] = 0.f;
        cb[j * 28 + 27] = 0.f;
    }
    __syncthreads();

    const int t0 = blockIdx.x * 1024 + tid;   // sibling token: t0 + 512
    ull f0[13], f1[13];
    {
        const float* fv = g_vq + t0 * 25;
#pragma unroll
        for (int i = 0; i < 12; ++i) f0[i] = f2pk(fv[2 * i], fv[2 * i + 1]);
        f0[12] = f2pk(fv[24], -1.0f);
        const float* gv = g_vq + (t0 + 512) * 25;
#pragma unroll
        for (int i = 0; i < 12; ++i) f1[i] = f2pk(gv[2 * i], gv[2 * i + 1]);
        f1[12] = f2pk(gv[24], -1.0f);
    }

    float best0 = -3.402823e38f, best1 = -3.402823e38f;
    int bi0 = 0, bi1 = 0;
    for (int j = 0; j < 1024; ++j) {
        const ulonglong2* row = reinterpret_cast<const ulonglong2*>(cb + j * 28);
        ulonglong2 v0 = row[0], v1 = row[1], v2 = row[2];
        ulonglong2 v3 = row[3], v4 = row[4], v5 = row[5];
        ull v6 = *(const ull*)(cb + j * 28 + 24);   // (c24, 0.5||c||^2)
        ull a0 = f2mul(f0[0], v0.x);
        ull c0 = f2mul(f0[1], v0.y);
        ull a1 = f2mul(f1[0], v0.x);
        ull c1 = f2mul(f1[1], v0.y);
        a0 = f2fma(f0[2], v1.x, a0);  c0 = f2fma(f0[3], v1.y, c0);
        a1 = f2fma(f1[2], v1.x, a1);  c1 = f2fma(f1[3], v1.y, c1);
        a0 = f2fma(f0[4], v2.x, a0);  c0 = f2fma(f0[5], v2.y, c0);
        a1 = f2fma(f1[4], v2.x, a1);  c1 = f2fma(f1[5], v2.y, c1);
        a0 = f2fma(f0[6], v3.x, a0);  c0 = f2fma(f0[7], v3.y, c0);
        a1 = f2fma(f1[6], v3.x, a1);  c1 = f2fma(f1[7], v3.y, c1);
        a0 = f2fma(f0[8], v4.x, a0);  c0 = f2fma(f0[9], v4.y, c0);
        a1 = f2fma(f1[8], v4.x, a1);  c1 = f2fma(f1[9], v4.y, c1);
        a0 = f2fma(f0[10], v5.x, a0); c0 = f2fma(f0[11], v5.y, c0);
        a1 = f2fma(f1[10], v5.x, a1); c1 = f2fma(f1[11], v5.y, c1);
        a0 = f2fma(f0[12], v6, a0);
        a1 = f2fma(f1[12], v6, a1);
        float sc0 = f2sum(f2add(a0, c0));
        float sc1 = f2sum(f2add(a1, c1));
        if (sc0 > best0) { best0 = sc0; bi0 = j; }   // strict > == first-argmin
        if (sc1 > best1) { best1 = sc1; bi1 = j; }
    }
    g_ind[t0] = bi0;
    g_ind[t0 + 512] = bi1;

    // exact commitment-loss contributions
    float ls = 0.f;
    {
        const float* rr = cb + bi0 * 28;
#pragma unroll
        for (int i = 0; i < 12; ++i) {
            float lo, hi; f2un(f0[i], lo, hi);
            float d0 = rr[2 * i] - lo;     ls = fmaf(d0, d0, ls);
            float d1 = rr[2 * i + 1] - hi; ls = fmaf(d1, d1, ls);
        }
        float lo, hi; f2un(f0[12], lo, hi);
        float d = rr[24] - lo; ls = fmaf(d, d, ls);
    }
    {
        const float* rr = cb + bi1 * 28;
#pragma unroll
        for (int i = 0; i < 12; ++i) {
            float lo, hi; f2un(f1[i], lo, hi);
            float d0 = rr[2 * i] - lo;     ls = fmaf(d0, d0, ls);
            float d1 = rr[2 * i + 1] - hi; ls = fmaf(d1, d1, ls);
        }
        float lo, hi; f2un(f1[12], lo, hi);
        float d = rr[24] - lo; ls = fmaf(d, d, ls);
    }
#pragma unroll
    for (int off = 16; off; off >>= 1) ls += __shfl_down_sync(0xffffffffu, ls, off);
    if ((tid & 31) == 0) sred[tid >> 5] = ls;
    __syncthreads();
    if (tid == 0) {
        float s = 0.f;
#pragma unroll
        for (int w = 0; w < 16; ++w) s += sred[w];
        g_lp[blockIdx.x] = s;
    }
}

__global__ void __launch_bounds__(128) kD2(float* __restrict__ out) {
    __shared__ float sred[4];
    const int tid = threadIdx.x;
    float s = g_lp[tid];
#pragma unroll
    for (int off = 16; off; off >>= 1) s += __shfl_down_sync(0xffffffffu, s, off);
    if ((tid & 31) == 0) sred[tid >> 5] = s;
    __syncthreads();
    if (tid == 0) {
        float t = 0.f;
#pragma unroll
        for (int w = 0; w < 4; ++w) t += sred[w];
        out[0] = t * (0.25f / 3276800.0f);
    }
}

// ---------------------------------------------------------------------------
// kE: gather codes, trans 1x1 (f32x2 s-pairs), pose head.  (R6 verbatim)
// ---------------------------------------------------------------------------
#define SMEM_E_FLOATS (3328 + 12288 + 2400)
#define KP_OFF (1 + 1228800)
__global__ void __launch_bounds__(512) kE(const float* __restrict__ codebook,
                                          const float* __restrict__ tw,
                                          const float* __restrict__ tb,
                                          const float* __restrict__ w1,
                                          const float* __restrict__ b1,
                                          const float* __restrict__ w2,
                                          const float* __restrict__ b2,
                                          float* __restrict__ out) {
    extern __shared__ float sm[];
    float* zr  = sm;            // 128 x 26 (col 25 = 0 pad)
    float* tws = zr + 3328;     // 12288
    float* lat = tws + 12288;   // 96 x 25
    __shared__ float part[512];
    __shared__ float hid[32];
    const int bb = blockIdx.x;
    const int tid = threadIdx.x;

    {
        const float4* s4 = (const float4*)tw;
        float4* d4 = (float4*)tws;
        for (int i = tid; i < 3072; i += 512) d4[i] = s4[i];
    }
    for (int el = tid; el < 3328; el += 512) {
        int i = el / 26, k = el % 26;
        float v = 0.f;
        if (k < 25) {
            int ci = g_ind[bb * 128 + i];
            v = codebook[ci * 25 + k];
        }
        zr[el] = v;
    }
    __syncthreads();

    for (int item = tid; item < 1248; item += 512) {
        const int oc = item / 13;
        const int s = (item % 13) * 2;
        ull acc = f2pk(0.f, 0.f);
#pragma unroll 4
        for (int i = 0; i < 128; ++i) {
            ull w = f2dup(tws[i * 96 + oc]);
            ull z = *(const ull*)(zr + i * 26 + s);
            acc = f2fma(w, z, acc);
        }
        float lo, hi; f2un(acc, lo, hi);
        const float bo = tb[oc];
        const float v0 = lo + bo;
        lat[oc * 25 + s] = v0;
        g_lat[bb * 2400 + oc * 25 + s] = v0;
        if (s + 1 < 25) {
            const float v1 = hi + bo;
            lat[oc * 25 + s + 1] = v1;
            g_lat[bb * 2400 + oc * 25 + s + 1] = v1;
        }
    }
    __syncthreads();

    const int warp = tid >> 5, lane = tid & 31;
    float a = 0.f;
    const int fbeg = warp * 150, fend = fbeg + 150;
    for (int f = fbeg; f < fend; ++f) a = fmaf(lat[f], w1[f * 32 + lane], a);
    part[warp * 32 + lane] = a;
    __syncthreads();
    if (tid < 32) {
        float s = b1[tid];
#pragma unroll
        for (int w = 0; w < 16; ++w) s += part[w * 32 + tid];
        hid[tid] = fmaxf(s, 0.f);
    }
    __syncthreads();
    if (tid < 36) {
        float acc = b2[tid];
#pragma unroll
        for (int h = 0; h < 32; ++h) acc = fmaf(hid[h], w2[h * 36 + tid], acc);
        out[KP_OFF + bb * 36 + tid] = acc;
    }
}

// ---------------------------------------------------------------------------
// kF: unpool2 + dec1 (row-based, ic-split partials) + relu + unpool1 + dec2.
// grid=1024, block=480.  (R9 verbatim)
// ---------------------------------------------------------------------------
#define SMEM_F_FLOATS (13824 + 27648 + 12800 + 864)
__global__ void __launch_bounds__(480) kF(const float* __restrict__ db1,
                                          const float* __restrict__ dw2,
                                          const float* __restrict__ db2,
                                          float* __restrict__ out) {
    extern __shared__ float sm[];
    float* u2p = sm;               // 96 x 12 x 12
    float* w1t = u2p + 13824;      // 27648, [(ic*9+k)][32]
    float* uni = w1t + 27648;      // 12800: partials then u1
    float* w2s = uni + 12800;      // 864
    ull*   part = (ull*)uni;       // 4800 ull used
    __shared__ float b1s[32];
    __shared__ float b2s[3];
    const int bb = blockIdx.x;
    const int tid = threadIdx.x;

    for (int i = tid; i < 13824; i += 480) u2p[i] = 0.f;
    if (tid < 32) b1s[tid] = db1[tid];
    if (tid < 3) b2s[tid] = db2[tid];
    {
        const float4* s4 = (const float4*)g_w1t;
        float4* d4 = (float4*)w1t;
        for (int i = tid; i < 6912; i += 480) d4[i] = s4[i];
    }
    {
        const float4* s4 = (const float4*)dw2;
        float4* d4 = (float4*)w2s;
        for (int i = tid; i < 216; i += 480) d4[i] = s4[i];
    }
    __syncthreads();

    for (int el = tid; el < 2400; el += 480) {
        int c = el / 25, s = el % 25, py = s / 5, px = s % 5;
        float v = g_lat[bb * 2400 + el];
        int ii = g_i2[bb * 2400 + el];
        u2p[c * 144 + (2 * py + (ii >> 1) + 1) * 12 + (2 * px + (ii & 1) + 1)] = v;
    }
    __syncthreads();

    {
        const int wrp = tid / 32;        // 0..14
        const int icg = wrp / 5;         // 0..2
        const int prow = wrp % 5;        // 0..4
        const int oc = tid % 32;
        const float* tile = u2p + (2 * prow) * 12;
        ull acc0[5], acc1[5];
#pragma unroll
        for (int k = 0; k < 5; ++k) { acc0[k] = 0ull; acc1[k] = 0ull; }
        const int ic0 = icg * 32;
        for (int ic = ic0; ic < ic0 + 32; ++ic) {
            const float* wq = w1t + ic * 9 * 32 + oc;
            ull w0 = f2dup(wq[0]),   w1 = f2dup(wq[32]),  w2 = f2dup(wq[64]);
            ull w3 = f2dup(wq[96]),  w4 = f2dup(wq[128]), w5 = f2dup(wq[160]);
            ull w6 = f2dup(wq[192]), w7 = f2dup(wq[224]), w8 = f2dup(wq[256]);
            const float* cp = tile + ic * 144;
            Row R;
            load_row(cp, R);
            apply_row(R, w0, w1, w2, acc0);
            load_row(cp + 12, R);
            apply_row(R, w3, w4, w5, acc0);
            apply_row(R, w0, w1, w2, acc1);
            load_row(cp + 24, R);
            apply_row(R, w6, w7, w8, acc0);
            apply_row(R, w3, w4, w5, acc1);
            load_row(cp + 36, R);
            apply_row(R, w6, w7, w8, acc1);
        }
#pragma unroll
        for (int k = 0; k < 5; ++k) {
            part[(2 * k + 0) * 480 + tid] = acc0[k];
            part[(2 * k + 1) * 480 + tid] = acc1[k];
        }
    }
    __syncthreads();

    ull vv[10];
    if (tid < 160) {
        const int oc = tid % 32;
        const ull bco = f2dup(b1s[oc]);
#pragma unroll
        for (int q = 0; q < 10; ++q) {
            ull p0 = part[q * 480 + 0 * 160 + tid];
            ull p1 = part[q * 480 + 1 * 160 + tid];
            ull p2 = part[q * 480 + 2 * 160 + tid];
            vv[q] = f2add(f2add(f2add(bco, p0), p1), p2);
        }
    }
    __syncthreads();
    for (int i = tid; i < 12800; i += 480) uni[i] = 0.f;   // uni becomes u1
    __syncthreads();
    if (tid < 160) {
        const int prow = tid / 32;
        const int oc = tid % 32;
#pragma unroll
        for (int k = 0; k < 5; ++k)
#pragma unroll
            for (int dy = 0; dy < 2; ++dy) {
                float lo, hi; f2un(vv[2 * k + dy], lo, hi);
                const int y = 2 * prow + dy;
#pragma unroll
                for (int dx = 0; dx < 2; ++dx) {
                    const int x = 2 * k + dx;
                    float v = fmaxf(dx == 0 ? lo : hi, 0.f);
                    int ii = g_i1[bb * 3200 + oc * 100 + y * 10 + x];
                    uni[oc * 400 + (2 * y + (ii >> 1)) * 20 + (2 * x + (ii & 1))] = v;
                }
            }
    }
    __syncthreads();

    for (int o = tid; o < 1200; o += 480) {
        const int oc = o / 400;
        const int r = o % 400;
        const int y = r / 20, x = r % 20;
        float acc = b2s[oc];
        for (int ic = 0; ic < 32; ++ic) {
            const float* wp = w2s + (oc * 32 + ic) * 9;
            const float* up = uni + ic * 400;
#pragma unroll
            for (int kh = 0; kh < 3; ++kh) {
                const int yy = y + kh - 1;
                if ((unsigned)yy < 20u) {
#pragma unroll
                    for (int kw = 0; kw < 3; ++kw) {
                        const int xx = x + kw - 1;
                        if ((unsigned)xx < 20u)
                            acc = fmaf(wp[kh * 3 + kw], up[yy * 20 + xx], acc);
                    }
                }
            }
        }
        out[1 + bb * 1200 + o] = acc;
    }
}

// ---------------------------------------------------------------------------
extern "C" void kernel_launch(void* const* d_in, const int* in_sizes, int n_in,
                              void* d_out, int out_size) {
    const float* x    = (const float*)d_in[0];
    const float* e1w  = (const float*)d_in[1];
    const float* e1b  = (const float*)d_in[2];
    const float* e2w  = (const float*)d_in[3];
    const float* e2b  = (const float*)d_in[4];
    const float* prew = (const float*)d_in[5];
    const float* preb = (const float*)d_in[6];
    const float* cbk  = (const float*)d_in[7];
    const float* trw  = (const float*)d_in[8];
    const float* trb  = (const float*)d_in[9];
    const float* d1w  = (const float*)d_in[10];
    const float* d1b  = (const float*)d_in[11];
    const float* d2w  = (const float*)d_in[12];
    const float* d2b  = (const float*)d_in[13];
    const float* hw1  = (const float*)d_in[14];
    const float* hb1  = (const float*)d_in[15];
    const float* hw2  = (const float*)d_in[16];
    const float* hb2  = (const float*)d_in[17];
    float* out = (float*)d_out;

    cudaFuncSetAttribute(kB, cudaFuncAttributeMaxDynamicSharedMemorySize, SMEM_B_FLOATS * 4);
    cudaFuncSetAttribute(kD, cudaFuncAttributeMaxDynamicSharedMemorySize, SMEM_D_FLOATS * 4);
    cudaFuncSetAttribute(kE, cudaFuncAttributeMaxDynamicSharedMemorySize, SMEM_E_FLOATS * 4);
    cudaFuncSetAttribute(kF, cudaFuncAttributeMaxDynamicSharedMemorySize, SMEM_F_FLOATS * 4);

    kT<<<108, 512>>>(e2w, d1w);
    kA<<<NB, 256>>>(x, e1w, e1b);
    kB<<<512, 480, SMEM_B_FLOATS * 4>>>(e2b, prew, preb);
    kD<<<128, 512, SMEM_D_FLOATS * 4>>>(cbk);
    kD2<<<1, 128>>>(out);
    kE<<<NB, 512, SMEM_E_FLOATS * 4>>>(cbk, trw, trb, hw1, hb1, hw2, hb2, out);
    kF<<<NB, 480, SMEM_F_FLOATS * 4>>>(d1b, d2w, d2b, out);
}